// round 13
// baseline (speedup 1.0000x reference)
#include <cuda_runtime.h>
#include <cuda_fp16.h>
#include <cstdint>

#define B_ 8
#define T_ 200
#define U_ 100
#define H_ 512
#define V_ 1024
#define M_TOT (B_ * T_ * U_)          // 160000

__device__ __half g_ench [B_ * T_ * H_];   // 1.6 MB fp16
__device__ __half g_predh[B_ * U_ * H_];   // 0.8 MB fp16
__device__ __half g_wout [V_ * H_];        // 1.0 MB fp16
__device__ __half g_J    [(size_t)M_TOT * H_];  // 164 MB fp16: relu(enc+pred)

// ───────────── helpers ─────────────
__device__ __forceinline__ uint32_t smem_u32(const void* p) {
    uint32_t a;
    asm("{ .reg .u64 t; cvta.to.shared.u64 t, %1; cvt.u32.u64 %0, t; }" : "=r"(a) : "l"(p));
    return a;
}
__device__ __forceinline__ uint32_t pack_h2(float x, float y) {
    __half2 h = __floats2half2_rn(x, y);
    return *reinterpret_cast<uint32_t*>(&h);
}
#define CP_ASYNC16(dst, src) \
    asm volatile("cp.async.cg.shared.global [%0], [%1], 16;" :: "r"(dst), "l"(src) : "memory")
#define CP_COMMIT() asm volatile("cp.async.commit_group;" ::: "memory")
#define CP_WAIT1()  asm volatile("cp.async.wait_group 1;" ::: "memory")

#define LDMATRIX_X4(r0, r1, r2, r3, addr) \
    asm volatile("ldmatrix.sync.aligned.m8n8.x4.shared.b16 {%0,%1,%2,%3}, [%4];" \
                 : "=r"(r0), "=r"(r1), "=r"(r2), "=r"(r3) : "r"(addr))

#define MMA16816(c, a, b0, b1) \
    asm volatile("mma.sync.aligned.m16n8k16.row.col.f32.f16.f16.f32 " \
                 "{%0,%1,%2,%3}, {%4,%5,%6,%7}, {%8,%9}, {%0,%1,%2,%3};" \
                 : "+f"((c)[0]), "+f"((c)[1]), "+f"((c)[2]), "+f"((c)[3]) \
                 : "r"((a)[0]), "r"((a)[1]), "r"((a)[2]), "r"((a)[3]), "r"(b0), "r"(b1))

// ───────────── projections (fp32 math, fp16 output) ─────────────
__global__ __launch_bounds__(256) void proj_both_kernel(
    const float* __restrict__ encI, const float* __restrict__ WE, const float* __restrict__ bE,
    const float* __restrict__ predI, const float* __restrict__ WP, const float* __restrict__ bP,
    __half* __restrict__ encO, __half* __restrict__ predO)
{
    const float *A, *W, *bias; __half* out; int M, K;
    if (blockIdx.z == 0) { A = encI;  W = WE; bias = bE; out = encO;  M = 1600; K = 512; }
    else                 { A = predI; W = WP; bias = bP; out = predO; M = 800;  K = 640; }
    const int N = 512;
    const int m0 = blockIdx.y * 64;
    if (m0 >= M) return;
    const int n0 = blockIdx.x * 64;

    __shared__ float As[16][68];
    __shared__ float Ws[16][68];
    const int tid = threadIdx.x;
    const int tx = tid & 15, ty = tid >> 4;
    const int lm = tid >> 2;
    const int lk = (tid & 3) << 2;
    const int arow = m0 + lm;
    const float* Ap = A + (size_t)arow * K;
    const float* Wp = W + (size_t)(n0 + lm) * K;
    float acc[4][4] = {};

    for (int k0 = 0; k0 < K; k0 += 16) {
        float4 av = make_float4(0.f, 0.f, 0.f, 0.f);
        if (arow < M) av = *(const float4*)(Ap + k0 + lk);
        float4 wv = *(const float4*)(Wp + k0 + lk);
        As[lk+0][lm] = av.x; As[lk+1][lm] = av.y; As[lk+2][lm] = av.z; As[lk+3][lm] = av.w;
        Ws[lk+0][lm] = wv.x; Ws[lk+1][lm] = wv.y; Ws[lk+2][lm] = wv.z; Ws[lk+3][lm] = wv.w;
        __syncthreads();
        #pragma unroll
        for (int kk = 0; kk < 16; kk++) {
            float a[4], w[4];
            *(float4*)a = *(const float4*)&As[kk][ty << 2];
            *(float4*)w = *(const float4*)&Ws[kk][tx << 2];
            #pragma unroll
            for (int i = 0; i < 4; i++)
                #pragma unroll
                for (int j = 0; j < 4; j++)
                    acc[i][j] = fmaf(a[i], w[j], acc[i][j]);
        }
        __syncthreads();
    }
    float4 bv = *(const float4*)(bias + n0 + (tx << 2));
    #pragma unroll
    for (int i = 0; i < 4; i++) {
        int row = m0 + (ty << 2) + i;
        if (row < M) {
            uint2 h;
            h.x = pack_h2(acc[i][0] + bv.x, acc[i][1] + bv.y);
            h.y = pack_h2(acc[i][2] + bv.z, acc[i][3] + bv.w);
            *(uint2*)(out + (size_t)row * N + n0 + (tx << 2)) = h;
        }
    }
}

// ───────────── J = relu(enc + pred) fp16, plus W convert (folded) ──────────
// blocks [0, 40000): J granules.  blocks [40000, 40256): W_out fp32->fp16.
__global__ __launch_bounds__(256) void joint_a_kernel(const float* __restrict__ W)
{
    if (blockIdx.x >= 40000) {
        int i = ((blockIdx.x - 40000) * 256 + threadIdx.x) * 8;
        float4 a = *(const float4*)(W + i);
        float4 b = *(const float4*)(W + i + 4);
        uint4 o;
        o.x = pack_h2(a.x, a.y); o.y = pack_h2(a.z, a.w);
        o.z = pack_h2(b.x, b.y); o.w = pack_h2(b.z, b.w);
        *(uint4*)(g_wout + i) = o;
        return;
    }
    const int idx = blockIdx.x * 256 + threadIdx.x;
    const int r   = idx >> 6;
    const int seg = (idx & 63) << 3;
    const int bt  = r / U_;
    const int u   = r - bt * U_;
    const int bb  = bt / T_;
    uint4 e = *(const uint4*)(g_ench  + (size_t)bt * H_ + seg);
    uint4 p = *(const uint4*)(g_predh + ((size_t)bb * U_ + u) * H_ + seg);
    const __half2 z = __float2half2_rn(0.f);
    uint4 o;
    const uint32_t* eu = &e.x; const uint32_t* pu = &p.x; uint32_t* ou = &o.x;
    #pragma unroll
    for (int j = 0; j < 4; j++) {
        __half2 eh = *reinterpret_cast<const __half2*>(&eu[j]);
        __half2 ph = *reinterpret_cast<const __half2*>(&pu[j]);
        __half2 rh = __hmax2(__hadd2(eh, ph), z);
        ou[j] = *reinterpret_cast<uint32_t*>(&rh);
    }
    *(uint4*)(g_J + (size_t)r * H_ + seg) = o;
}

// ───────────── joint GEMM: BK=64, 3-stage ring, 8 warps (4m x 2n) ──────────
// CTA 128x128, 256 threads, warp tile 32x64 → 4 warps/SMSP at occ 2.
// Rows are 128B (64 halves), full SW128 swizzle: seg ^= (row & 7).
#define BK       64
#define NCHUNK   (H_ / BK)             // 8
#define A_SZ     (128 * BK * 2)        // 16384 B
#define B_SZ     (128 * BK * 2)        // 16384 B
#define STAGE_SZ (A_SZ + B_SZ)         // 32768 B
#define STAGES   3
#define SMEM_DYN (STAGES * STAGE_SZ)   // 98304 B

__global__ __launch_bounds__(256, 2) void joint_mma_kernel(
    const float* __restrict__ bout, float* __restrict__ out)
{
    extern __shared__ char smem[];
    const uint32_t smb = smem_u32(smem);

    const int tid  = threadIdx.x;
    const int wid  = tid >> 5, lane = tid & 31;
    const int wm   = wid & 3;           // warp m block (32 rows)
    const int wn   = wid >> 2;          // warp n block (64 cols)
    const int m0   = blockIdx.y * 128;
    const int n0   = blockIdx.x * 128;

    // ── loaders: 128 rows x 8 segs(16B) = 1024 granules each; 4/thread.
    //    granule g: row = (tid>>3) + 32g, kseg = tid&7 → off = ld0 + g*4096.
    const int lrow = tid >> 3;          // 0..31
    const int kseg = tid & 7;
    const __half* jp0 = g_J    + (size_t)(m0 + lrow) * H_ + kseg * 8;
    const __half* wp0 = g_wout + (size_t)(n0 + lrow) * H_ + kseg * 8;
    const uint32_t ld0 = (uint32_t)lrow * 128u + ((uint32_t)(kseg ^ (lrow & 7)) << 4);

    // ── ldmatrix bases (swizzle key is lane-only: row & 7 == lane & 7)
    const uint32_t xkey = (uint32_t)(lane & 7);
    const int ahi = lane >> 4;                 // A k-octet selector
    const int bhi = (lane >> 3) & 1;           // B k-octet selector
    const uint32_t aab0 = smb + (uint32_t)(wm * 32 + (lane & 15)) * 128u;
    const uint32_t bab0 = smb + A_SZ + (uint32_t)(wn * 64 + (lane >> 4) * 8 + (lane & 7)) * 128u;

    float acc[2][8][4] = {};

    auto issue = [&](int c) {
        const uint32_t stb = smb + (uint32_t)(c % STAGES) * STAGE_SZ;
        const int k0 = c * BK;
        const __half* j = jp0 + k0;
        const __half* w = wp0 + k0;
        #pragma unroll
        for (int g = 0; g < 4; g++)
            CP_ASYNC16(stb + ld0 + g * 4096u, j + (size_t)g * 32 * H_);
        #pragma unroll
        for (int g = 0; g < 4; g++)
            CP_ASYNC16(stb + A_SZ + ld0 + g * 4096u, w + (size_t)g * 32 * H_);
        CP_COMMIT();
    };
    auto compute = [&](int st) {
        const uint32_t stb = (uint32_t)st * STAGE_SZ;
        #pragma unroll
        for (int ks = 0; ks < 4; ks++) {
            const uint32_t segA = ((uint32_t)(ks * 2 + ahi) ^ xkey) << 4;
            const uint32_t segB = ((uint32_t)(ks * 2 + bhi) ^ xkey) << 4;
            uint32_t b[4][4];
            #pragma unroll
            for (int p = 0; p < 4; p++)
                LDMATRIX_X4(b[p][0], b[p][1], b[p][2], b[p][3],
                            bab0 + stb + p * 2048u + segB);
            #pragma unroll
            for (int mt = 0; mt < 2; mt++) {
                uint32_t a[4];
                LDMATRIX_X4(a[0], a[1], a[2], a[3],
                            aab0 + stb + mt * 2048u + segA);
                #pragma unroll
                for (int p = 0; p < 4; p++) {
                    MMA16816(acc[mt][2*p],   a, b[p][0], b[p][1]);
                    MMA16816(acc[mt][2*p+1], a, b[p][2], b[p][3]);
                }
            }
        }
    };

    // ── prologue: 2 chunks in flight
    issue(0); issue(1);

    // ── mainloop: wait(c) → barrier → issue(c+2) → compute(c)
    for (int c = 0; c < NCHUNK; ++c) {
        CP_WAIT1();
        __syncthreads();
        if (c + 2 < NCHUNK) issue(c + 2);
        compute(c % STAGES);
    }

    // ── epilogue: direct coalesced STG
    const int r0 = m0 + wm * 32 + (lane >> 2);
    const int c0 = n0 + wn * 64 + (lane & 3) * 2;
    float2 bb[8];
    #pragma unroll
    for (int nt = 0; nt < 8; nt++) bb[nt] = *(const float2*)(bout + c0 + nt * 8);
    #pragma unroll
    for (int mt = 0; mt < 2; mt++)
        #pragma unroll
        for (int rh = 0; rh < 2; rh++) {
            const size_t rbase = (size_t)(r0 + mt * 16 + rh * 8) * V_ + c0;
            #pragma unroll
            for (int nt = 0; nt < 8; nt++) {
                float2 v;
                v.x = (acc[mt][nt][rh * 2 + 0] + bb[nt].x) * 0.1f;
                v.y = (acc[mt][nt][rh * 2 + 1] + bb[nt].y) * 0.1f;
                *(float2*)(out + rbase + nt * 8) = v;
            }
        }
}

// ───────────── launch ─────────────
extern "C" void kernel_launch(void* const* d_in, const int* in_sizes, int n_in,
                              void* d_out, int out_size)
{
    const float* enc_in  = (const float*)d_in[0];
    const float* pred_in = (const float*)d_in[1];
    const float* W_enc   = (const float*)d_in[2];
    const float* b_enc   = (const float*)d_in[3];
    const float* W_pred  = (const float*)d_in[4];
    const float* b_pred  = (const float*)d_in[5];
    const float* W_out   = (const float*)d_in[6];
    const float* b_out   = (const float*)d_in[7];
    float* out = (float*)d_out;

    __half *genc = nullptr, *gpred = nullptr;
    cudaGetSymbolAddress((void**)&genc, g_ench);
    cudaGetSymbolAddress((void**)&gpred, g_predh);

    cudaFuncSetAttribute(joint_mma_kernel,
                         cudaFuncAttributeMaxDynamicSharedMemorySize, SMEM_DYN);

    proj_both_kernel<<<dim3(8, 25, 2), 256>>>(
        enc_in, W_enc, b_enc, pred_in, W_pred, b_pred, genc, gpred);
    joint_a_kernel<<<40256, 256>>>(W_out);
    // joint: M=160000 -> 1250 tiles of 128, N=1024 -> 8 tiles of 128
    joint_mma_kernel<<<dim3(8, 1250), 256, SMEM_DYN>>>(b_out, out);
}

// round 14
// speedup vs baseline: 1.0400x; 1.0400x over previous
#include <cuda_runtime.h>
#include <cuda_fp16.h>
#include <cstdint>

#define B_ 8
#define T_ 200
#define U_ 100
#define H_ 512
#define V_ 1024
#define M_TOT (B_ * T_ * U_)          // 160000

__device__ __half g_ench [B_ * T_ * H_];   // 1.6 MB fp16
__device__ __half g_predh[B_ * U_ * H_];   // 0.8 MB fp16
__device__ __half g_wout [V_ * H_];        // 1.0 MB fp16
__device__ __half g_J    [(size_t)M_TOT * H_];  // 164 MB fp16: relu(enc+pred)

// ───────────── helpers ─────────────
__device__ __forceinline__ uint32_t smem_u32(const void* p) {
    uint32_t a;
    asm("{ .reg .u64 t; cvta.to.shared.u64 t, %1; cvt.u32.u64 %0, t; }" : "=r"(a) : "l"(p));
    return a;
}
__device__ __forceinline__ uint32_t pack_h2(float x, float y) {
    __half2 h = __floats2half2_rn(x, y);
    return *reinterpret_cast<uint32_t*>(&h);
}
#define CP_ASYNC16(dst, src) \
    asm volatile("cp.async.cg.shared.global [%0], [%1], 16;" :: "r"(dst), "l"(src) : "memory")
#define CP_COMMIT() asm volatile("cp.async.commit_group;" ::: "memory")
#define CP_WAIT1()  asm volatile("cp.async.wait_group 1;" ::: "memory")

#define LDMATRIX_X4(r0, r1, r2, r3, addr) \
    asm volatile("ldmatrix.sync.aligned.m8n8.x4.shared.b16 {%0,%1,%2,%3}, [%4];" \
                 : "=r"(r0), "=r"(r1), "=r"(r2), "=r"(r3) : "r"(addr))

#define MMA16816(c, a, b0, b1) \
    asm volatile("mma.sync.aligned.m16n8k16.row.col.f32.f16.f16.f32 " \
                 "{%0,%1,%2,%3}, {%4,%5,%6,%7}, {%8,%9}, {%0,%1,%2,%3};" \
                 : "+f"((c)[0]), "+f"((c)[1]), "+f"((c)[2]), "+f"((c)[3]) \
                 : "r"((a)[0]), "r"((a)[1]), "r"((a)[2]), "r"((a)[3]), "r"(b0), "r"(b1))

// ───────────── projections (fp32 math, fp16 output) ─────────────
__global__ __launch_bounds__(256) void proj_both_kernel(
    const float* __restrict__ encI, const float* __restrict__ WE, const float* __restrict__ bE,
    const float* __restrict__ predI, const float* __restrict__ WP, const float* __restrict__ bP,
    __half* __restrict__ encO, __half* __restrict__ predO)
{
    const float *A, *W, *bias; __half* out; int M, K;
    if (blockIdx.z == 0) { A = encI;  W = WE; bias = bE; out = encO;  M = 1600; K = 512; }
    else                 { A = predI; W = WP; bias = bP; out = predO; M = 800;  K = 640; }
    const int N = 512;
    const int m0 = blockIdx.y * 64;
    if (m0 >= M) return;
    const int n0 = blockIdx.x * 64;

    __shared__ float As[16][68];
    __shared__ float Ws[16][68];
    const int tid = threadIdx.x;
    const int tx = tid & 15, ty = tid >> 4;
    const int lm = tid >> 2;
    const int lk = (tid & 3) << 2;
    const int arow = m0 + lm;
    const float* Ap = A + (size_t)arow * K;
    const float* Wp = W + (size_t)(n0 + lm) * K;
    float acc[4][4] = {};

    for (int k0 = 0; k0 < K; k0 += 16) {
        float4 av = make_float4(0.f, 0.f, 0.f, 0.f);
        if (arow < M) av = *(const float4*)(Ap + k0 + lk);
        float4 wv = *(const float4*)(Wp + k0 + lk);
        As[lk+0][lm] = av.x; As[lk+1][lm] = av.y; As[lk+2][lm] = av.z; As[lk+3][lm] = av.w;
        Ws[lk+0][lm] = wv.x; Ws[lk+1][lm] = wv.y; Ws[lk+2][lm] = wv.z; Ws[lk+3][lm] = wv.w;
        __syncthreads();
        #pragma unroll
        for (int kk = 0; kk < 16; kk++) {
            float a[4], w[4];
            *(float4*)a = *(const float4*)&As[kk][ty << 2];
            *(float4*)w = *(const float4*)&Ws[kk][tx << 2];
            #pragma unroll
            for (int i = 0; i < 4; i++)
                #pragma unroll
                for (int j = 0; j < 4; j++)
                    acc[i][j] = fmaf(a[i], w[j], acc[i][j]);
        }
        __syncthreads();
    }
    float4 bv = *(const float4*)(bias + n0 + (tx << 2));
    #pragma unroll
    for (int i = 0; i < 4; i++) {
        int row = m0 + (ty << 2) + i;
        if (row < M) {
            uint2 h;
            h.x = pack_h2(acc[i][0] + bv.x, acc[i][1] + bv.y);
            h.y = pack_h2(acc[i][2] + bv.z, acc[i][3] + bv.w);
            *(uint2*)(out + (size_t)row * N + n0 + (tx << 2)) = h;
        }
    }
}

// ───────────── J = relu(enc + pred) fp16, plus W convert (folded) ──────────
__global__ __launch_bounds__(256) void joint_a_kernel(const float* __restrict__ W)
{
    if (blockIdx.x >= 40000) {
        int i = ((blockIdx.x - 40000) * 256 + threadIdx.x) * 8;
        float4 a = *(const float4*)(W + i);
        float4 b = *(const float4*)(W + i + 4);
        uint4 o;
        o.x = pack_h2(a.x, a.y); o.y = pack_h2(a.z, a.w);
        o.z = pack_h2(b.x, b.y); o.w = pack_h2(b.z, b.w);
        *(uint4*)(g_wout + i) = o;
        return;
    }
    const int idx = blockIdx.x * 256 + threadIdx.x;
    const int r   = idx >> 6;
    const int seg = (idx & 63) << 3;
    const int bt  = r / U_;
    const int u   = r - bt * U_;
    const int bb  = bt / T_;
    uint4 e = *(const uint4*)(g_ench  + (size_t)bt * H_ + seg);
    uint4 p = *(const uint4*)(g_predh + ((size_t)bb * U_ + u) * H_ + seg);
    const __half2 z = __float2half2_rn(0.f);
    uint4 o;
    const uint32_t* eu = &e.x; const uint32_t* pu = &p.x; uint32_t* ou = &o.x;
    #pragma unroll
    for (int j = 0; j < 4; j++) {
        __half2 eh = *reinterpret_cast<const __half2*>(&eu[j]);
        __half2 ph = *reinterpret_cast<const __half2*>(&pu[j]);
        __half2 rh = __hmax2(__hadd2(eh, ph), z);
        ou[j] = *reinterpret_cast<uint32_t*>(&rh);
    }
    *(uint4*)(g_J + (size_t)r * H_ + seg) = o;
}

// ───────────── persistent joint GEMM ─────────────
// Grid = 296 persistent CTAs (2/SM). Each CTA owns a FIXED n-tile
// (296 % 8 == 0) and walks m-tiles with stride 37. CTA 128x128, 128 threads
// (4 warps 2x2, warp tile 64x64), BK=64, 3-stage ring, 1 barrier/chunk.
// Every iteration commits a group (empty ones complete in order), so
// wait_group 1 always proves the current chunk's loads are done.
#define BK       64
#define NCHUNK   (H_ / BK)             // 8
#define A_SZ     (128 * BK * 2)        // 16384 B
#define B_SZ     (128 * BK * 2)        // 16384 B
#define STAGE_SZ (A_SZ + B_SZ)         // 32768 B
#define STAGES   3
#define SMEM_DYN (STAGES * STAGE_SZ)   // 98304 B
#define NCTA     296
#define M_TILES  1250
#define M_STRIDE (NCTA / 8)            // 37

__global__ __launch_bounds__(128, 2) void joint_mma_kernel(
    const float* __restrict__ bout, float* __restrict__ out)
{
    extern __shared__ char smem[];
    const uint32_t smb = smem_u32(smem);

    const int tid  = threadIdx.x;
    const int wid  = tid >> 5, lane = tid & 31;
    const int wm   = wid & 1;
    const int wn   = wid >> 1;
    const int n_idx = blockIdx.x & 7;
    const int m_idx0 = blockIdx.x >> 3;        // 0..36
    const int n0   = n_idx * 128;

    // ── loaders: 128 rows x 8 segs(16B); 16 cp.async per thread per chunk
    const int lrow = tid >> 3;                 // 0..15
    const int kseg = tid & 7;
    const uint32_t ld0 = (uint32_t)lrow * 128u + ((uint32_t)(kseg ^ (lrow & 7)) << 4);
    const __half* wp0 = g_wout + (size_t)(n0 + lrow) * H_ + kseg * 8;   // fixed
    const __half* jp0 = g_J + (size_t)(m_idx0 * 128 + lrow) * H_ + kseg * 8;
    const size_t JSTRIDE = (size_t)M_STRIDE * 128 * H_;

    // ── ldmatrix bases
    const uint32_t xkey = (uint32_t)(lane & 7);
    const int ahi = lane >> 4;
    const int bhi = (lane >> 3) & 1;
    const uint32_t aab0 = smb + (uint32_t)(wm * 64 + (lane & 15)) * 128u;
    const uint32_t bab0 = smb + A_SZ + (uint32_t)(wn * 64 + (lane >> 4) * 8 + (lane & 7)) * 128u;

    // ── bias: fixed n-tile → hoisted for the whole kernel
    const int c0 = n0 + wn * 64 + (lane & 3) * 2;
    float2 bb[8];
    #pragma unroll
    for (int nt = 0; nt < 8; nt++) bb[nt] = *(const float2*)(bout + c0 + nt * 8);

    float acc[4][8][4] = {};

    auto issueJW = [&](const __half* j, const __half* w, int stage) {
        const uint32_t stb = smb + (uint32_t)stage * STAGE_SZ;
        #pragma unroll
        for (int g = 0; g < 8; g++)
            CP_ASYNC16(stb + ld0 + g * 2048u, j + (size_t)g * 16 * H_);
        #pragma unroll
        for (int g = 0; g < 8; g++)
            CP_ASYNC16(stb + A_SZ + ld0 + g * 2048u, w + (size_t)g * 16 * H_);
    };
    auto compute = [&](int st) {
        const uint32_t stb = (uint32_t)st * STAGE_SZ;
        #pragma unroll
        for (int ks = 0; ks < 4; ks++) {
            const uint32_t segA = ((uint32_t)(ks * 2 + ahi) ^ xkey) << 4;
            const uint32_t segB = ((uint32_t)(ks * 2 + bhi) ^ xkey) << 4;
            uint32_t b[4][4];
            #pragma unroll
            for (int p = 0; p < 4; p++)
                LDMATRIX_X4(b[p][0], b[p][1], b[p][2], b[p][3],
                            bab0 + stb + p * 2048u + segB);
            #pragma unroll
            for (int mt = 0; mt < 4; mt++) {
                uint32_t a[4];
                LDMATRIX_X4(a[0], a[1], a[2], a[3],
                            aab0 + stb + mt * 2048u + segA);
                #pragma unroll
                for (int p = 0; p < 4; p++) {
                    MMA16816(acc[mt][2*p],   a, b[p][0], b[p][1]);
                    MMA16816(acc[mt][2*p+1], a, b[p][2], b[p][3]);
                }
            }
        }
    };

    // ── prologue: first tile's chunks 0,1
    int stIss = 0, stCmp = 0;
    issueJW(jp0,            wp0,      stIss); CP_COMMIT(); stIss = (stIss + 1) % STAGES;
    issueJW(jp0 + BK,       wp0 + BK, stIss); CP_COMMIT(); stIss = (stIss + 1) % STAGES;

    // ── persistent tile loop
    for (int mi = m_idx0; mi < M_TILES; mi += M_STRIDE) {
        const __half* jp_next = jp0 + JSTRIDE;
        const bool has_next = (mi + M_STRIDE) < M_TILES;

        #pragma unroll
        for (int c = 0; c < NCHUNK; ++c) {
            CP_WAIT1();
            __syncthreads();
            if (c < NCHUNK - 2) {
                issueJW(jp0 + (c + 2) * BK, wp0 + (c + 2) * BK, stIss);
                stIss = (stIss + 1) % STAGES;
            } else if (has_next) {
                issueJW(jp_next + (c - 6) * BK, wp0 + (c - 6) * BK, stIss);
                stIss = (stIss + 1) % STAGES;
            }
            CP_COMMIT();   // ALWAYS commit (empty group ok) so WAIT1 stays sound
            compute(stCmp);
            stCmp = (stCmp + 1) % STAGES;
        }

        // ── epilogue for tile mi (overlaps next tile's chunk-0/1 loads)
        const int r0 = mi * 128 + wm * 64 + (lane >> 2);
        #pragma unroll
        for (int mt = 0; mt < 4; mt++)
            #pragma unroll
            for (int rh = 0; rh < 2; rh++) {
                const size_t rbase = (size_t)(r0 + mt * 16 + rh * 8) * V_ + c0;
                #pragma unroll
                for (int nt = 0; nt < 8; nt++) {
                    float2 v;
                    v.x = (acc[mt][nt][rh * 2 + 0] + bb[nt].x) * 0.1f;
                    v.y = (acc[mt][nt][rh * 2 + 1] + bb[nt].y) * 0.1f;
                    *(float2*)(out + rbase + nt * 8) = v;
                }
            }
        #pragma unroll
        for (int mt = 0; mt < 4; mt++)
            #pragma unroll
            for (int p = 0; p < 8; p++)
                #pragma unroll
                for (int q = 0; q < 4; q++)
                    acc[mt][p][q] = 0.f;

        jp0 = jp_next;
    }
}

// ───────────── launch ─────────────
extern "C" void kernel_launch(void* const* d_in, const int* in_sizes, int n_in,
                              void* d_out, int out_size)
{
    const float* enc_in  = (const float*)d_in[0];
    const float* pred_in = (const float*)d_in[1];
    const float* W_enc   = (const float*)d_in[2];
    const float* b_enc   = (const float*)d_in[3];
    const float* W_pred  = (const float*)d_in[4];
    const float* b_pred  = (const float*)d_in[5];
    const float* W_out   = (const float*)d_in[6];
    const float* b_out   = (const float*)d_in[7];
    float* out = (float*)d_out;

    __half *genc = nullptr, *gpred = nullptr;
    cudaGetSymbolAddress((void**)&genc, g_ench);
    cudaGetSymbolAddress((void**)&gpred, g_predh);

    cudaFuncSetAttribute(joint_mma_kernel,
                         cudaFuncAttributeMaxDynamicSharedMemorySize, SMEM_DYN);

    proj_both_kernel<<<dim3(8, 25, 2), 256>>>(
        enc_in, W_enc, b_enc, pred_in, W_pred, b_pred, genc, gpred);
    joint_a_kernel<<<40256, 256>>>(W_out);
    joint_mma_kernel<<<NCTA, 128, SMEM_DYN>>>(b_out, out);
}

// round 15
// speedup vs baseline: 1.0572x; 1.0166x over previous
#include <cuda_runtime.h>
#include <cuda_fp16.h>
#include <cstdint>

#define B_ 8
#define T_ 200
#define U_ 100
#define H_ 512
#define V_ 1024
#define M_TOT (B_ * T_ * U_)          // 160000

__device__ __half g_ench [B_ * T_ * H_];   // 1.6 MB fp16
__device__ __half g_predh[B_ * U_ * H_];   // 0.8 MB fp16
__device__ __half g_wout [V_ * H_];        // 1.0 MB fp16
__device__ __half g_J    [(size_t)M_TOT * H_];  // 164 MB fp16: relu(enc+pred)

// ───────────── helpers ─────────────
__device__ __forceinline__ uint32_t smem_u32(const void* p) {
    uint32_t a;
    asm("{ .reg .u64 t; cvta.to.shared.u64 t, %1; cvt.u32.u64 %0, t; }" : "=r"(a) : "l"(p));
    return a;
}
__device__ __forceinline__ uint32_t pack_h2(float x, float y) {
    __half2 h = __floats2half2_rn(x, y);
    return *reinterpret_cast<uint32_t*>(&h);
}
#define CP_ASYNC16(dst, src) \
    asm volatile("cp.async.cg.shared.global [%0], [%1], 16;" :: "r"(dst), "l"(src) : "memory")
#define CP_COMMIT() asm volatile("cp.async.commit_group;" ::: "memory")
#define CP_WAIT1()  asm volatile("cp.async.wait_group 1;" ::: "memory")

#define LDMATRIX_X4(r0, r1, r2, r3, addr) \
    asm volatile("ldmatrix.sync.aligned.m8n8.x4.shared.b16 {%0,%1,%2,%3}, [%4];" \
                 : "=r"(r0), "=r"(r1), "=r"(r2), "=r"(r3) : "r"(addr))

#define MMA16816(c, a, b0, b1) \
    asm volatile("mma.sync.aligned.m16n8k16.row.col.f32.f16.f16.f32 " \
                 "{%0,%1,%2,%3}, {%4,%5,%6,%7}, {%8,%9}, {%0,%1,%2,%3};" \
                 : "+f"((c)[0]), "+f"((c)[1]), "+f"((c)[2]), "+f"((c)[3]) \
                 : "r"((a)[0]), "r"((a)[1]), "r"((a)[2]), "r"((a)[3]), "r"(b0), "r"(b1))

// ───────────── projections (fp32 math, fp16 output) ─────────────
__global__ __launch_bounds__(256) void proj_both_kernel(
    const float* __restrict__ encI, const float* __restrict__ WE, const float* __restrict__ bE,
    const float* __restrict__ predI, const float* __restrict__ WP, const float* __restrict__ bP,
    __half* __restrict__ encO, __half* __restrict__ predO)
{
    const float *A, *W, *bias; __half* out; int M, K;
    if (blockIdx.z == 0) { A = encI;  W = WE; bias = bE; out = encO;  M = 1600; K = 512; }
    else                 { A = predI; W = WP; bias = bP; out = predO; M = 800;  K = 640; }
    const int N = 512;
    const int m0 = blockIdx.y * 64;
    if (m0 >= M) return;
    const int n0 = blockIdx.x * 64;

    __shared__ float As[16][68];
    __shared__ float Ws[16][68];
    const int tid = threadIdx.x;
    const int tx = tid & 15, ty = tid >> 4;
    const int lm = tid >> 2;
    const int lk = (tid & 3) << 2;
    const int arow = m0 + lm;
    const float* Ap = A + (size_t)arow * K;
    const float* Wp = W + (size_t)(n0 + lm) * K;
    float acc[4][4] = {};

    for (int k0 = 0; k0 < K; k0 += 16) {
        float4 av = make_float4(0.f, 0.f, 0.f, 0.f);
        if (arow < M) av = *(const float4*)(Ap + k0 + lk);
        float4 wv = *(const float4*)(Wp + k0 + lk);
        As[lk+0][lm] = av.x; As[lk+1][lm] = av.y; As[lk+2][lm] = av.z; As[lk+3][lm] = av.w;
        Ws[lk+0][lm] = wv.x; Ws[lk+1][lm] = wv.y; Ws[lk+2][lm] = wv.z; Ws[lk+3][lm] = wv.w;
        __syncthreads();
        #pragma unroll
        for (int kk = 0; kk < 16; kk++) {
            float a[4], w[4];
            *(float4*)a = *(const float4*)&As[kk][ty << 2];
            *(float4*)w = *(const float4*)&Ws[kk][tx << 2];
            #pragma unroll
            for (int i = 0; i < 4; i++)
                #pragma unroll
                for (int j = 0; j < 4; j++)
                    acc[i][j] = fmaf(a[i], w[j], acc[i][j]);
        }
        __syncthreads();
    }
    float4 bv = *(const float4*)(bias + n0 + (tx << 2));
    #pragma unroll
    for (int i = 0; i < 4; i++) {
        int row = m0 + (ty << 2) + i;
        if (row < M) {
            uint2 h;
            h.x = pack_h2(acc[i][0] + bv.x, acc[i][1] + bv.y);
            h.y = pack_h2(acc[i][2] + bv.z, acc[i][3] + bv.w);
            *(uint2*)(out + (size_t)row * N + n0 + (tx << 2)) = h;
        }
    }
}

// ───────────── J = relu(enc + pred) fp16, plus W convert (folded) ──────────
__global__ __launch_bounds__(256) void joint_a_kernel(const float* __restrict__ W)
{
    if (blockIdx.x >= 40000) {
        int i = ((blockIdx.x - 40000) * 256 + threadIdx.x) * 8;
        float4 a = *(const float4*)(W + i);
        float4 b = *(const float4*)(W + i + 4);
        uint4 o;
        o.x = pack_h2(a.x, a.y); o.y = pack_h2(a.z, a.w);
        o.z = pack_h2(b.x, b.y); o.w = pack_h2(b.z, b.w);
        *(uint4*)(g_wout + i) = o;
        return;
    }
    const int idx = blockIdx.x * 256 + threadIdx.x;
    const int r   = idx >> 6;
    const int seg = (idx & 63) << 3;
    const int bt  = r / U_;
    const int u   = r - bt * U_;
    const int bb  = bt / T_;
    uint4 e = *(const uint4*)(g_ench  + (size_t)bt * H_ + seg);
    uint4 p = *(const uint4*)(g_predh + ((size_t)bb * U_ + u) * H_ + seg);
    const __half2 z = __float2half2_rn(0.f);
    uint4 o;
    const uint32_t* eu = &e.x; const uint32_t* pu = &p.x; uint32_t* ou = &o.x;
    #pragma unroll
    for (int j = 0; j < 4; j++) {
        __half2 eh = *reinterpret_cast<const __half2*>(&eu[j]);
        __half2 ph = *reinterpret_cast<const __half2*>(&pu[j]);
        __half2 rh = __hmax2(__hadd2(eh, ph), z);
        ou[j] = *reinterpret_cast<uint32_t*>(&rh);
    }
    *(uint4*)(g_J + (size_t)r * H_ + seg) = o;
}

// ───────────── joint GEMM: BK=64, 3-stage ring, frag double-buffering ──────
// CTA 128x128, 128 threads (4 warps 2x2, warp tile 64x64).
// Rows are 128B (64 halves), full SW128 swizzle: seg ^= (row & 7).
// compute() prefetches A(mt+1) during mt's MMA burst and B(ks+1)/A(0,ks+1)
// during the last burst, so every ldmatrix has a full MMA burst of cover.
#define BK       64
#define NCHUNK   (H_ / BK)             // 8
#define A_SZ     (128 * BK * 2)        // 16384 B
#define B_SZ     (128 * BK * 2)        // 16384 B
#define STAGE_SZ (A_SZ + B_SZ)         // 32768 B
#define STAGES   3
#define SMEM_DYN (STAGES * STAGE_SZ)   // 98304 B

__global__ __launch_bounds__(128, 2) void joint_mma_kernel(
    const float* __restrict__ bout, float* __restrict__ out)
{
    extern __shared__ char smem[];
    const uint32_t smb = smem_u32(smem);

    const int tid  = threadIdx.x;
    const int wid  = tid >> 5, lane = tid & 31;
    const int wm   = wid & 1;
    const int wn   = wid >> 1;
    const int m0   = blockIdx.y * 128;
    const int n0   = blockIdx.x * 128;

    // ── loaders: 128 rows x 8 segs(16B) = 1024 granules each; 8/thread.
    const int lrow = tid >> 3;
    const int kseg = tid & 7;
    const __half* jp0 = g_J    + (size_t)(m0 + lrow) * H_ + kseg * 8;
    const __half* wp0 = g_wout + (size_t)(n0 + lrow) * H_ + kseg * 8;
    const uint32_t ld0 = (uint32_t)lrow * 128u + ((uint32_t)(kseg ^ (lrow & 7)) << 4);

    // ── ldmatrix bases (swizzle key is lane-only: row & 7 == lane & 7)
    const uint32_t xkey = (uint32_t)(lane & 7);
    const int ahi = lane >> 4;
    const int bhi = (lane >> 3) & 1;
    const uint32_t aab0 = smb + (uint32_t)(wm * 64 + (lane & 15)) * 128u;
    const uint32_t bab0 = smb + A_SZ + (uint32_t)(wn * 64 + (lane >> 4) * 8 + (lane & 7)) * 128u;

    float acc[4][8][4] = {};

    auto issue = [&](int c) {
        const uint32_t stb = smb + (uint32_t)(c % STAGES) * STAGE_SZ;
        const int k0 = c * BK;
        const __half* j = jp0 + k0;
        const __half* w = wp0 + k0;
        #pragma unroll
        for (int g = 0; g < 8; g++)
            CP_ASYNC16(stb + ld0 + g * 2048u, j + (size_t)g * 16 * H_);
        #pragma unroll
        for (int g = 0; g < 8; g++)
            CP_ASYNC16(stb + A_SZ + ld0 + g * 2048u, w + (size_t)g * 16 * H_);
        CP_COMMIT();
    };

    auto compute = [&](int st) {
        const uint32_t stb = (uint32_t)st * STAGE_SZ;
        uint32_t bf[2][4][4];   // B frags, double-buffered by ks parity
        uint32_t af[2][4];      // A frags, double-buffered by mt parity

        // preload ks=0: all 4 B tiles + A(mt=0)
        {
            const uint32_t segB = ((uint32_t)bhi ^ xkey) << 4;
            #pragma unroll
            for (int p = 0; p < 4; p++)
                LDMATRIX_X4(bf[0][p][0], bf[0][p][1], bf[0][p][2], bf[0][p][3],
                            bab0 + stb + p * 2048u + segB);
            const uint32_t segA = ((uint32_t)ahi ^ xkey) << 4;
            LDMATRIX_X4(af[0][0], af[0][1], af[0][2], af[0][3],
                        aab0 + stb + segA);
        }

        #pragma unroll
        for (int ks = 0; ks < 4; ks++) {
            const int pb = ks & 1;
            #pragma unroll
            for (int mt = 0; mt < 4; mt++) {
                const int pa = mt & 1;
                // prefetch next fragments BEFORE this burst's MMAs
                if (mt < 3) {
                    const uint32_t segA = ((uint32_t)(ks * 2 + ahi) ^ xkey) << 4;
                    LDMATRIX_X4(af[pa ^ 1][0], af[pa ^ 1][1], af[pa ^ 1][2], af[pa ^ 1][3],
                                aab0 + stb + (mt + 1) * 2048u + segA);
                } else if (ks < 3) {
                    const uint32_t segB = ((uint32_t)((ks + 1) * 2 + bhi) ^ xkey) << 4;
                    #pragma unroll
                    for (int p = 0; p < 4; p++)
                        LDMATRIX_X4(bf[pb ^ 1][p][0], bf[pb ^ 1][p][1],
                                    bf[pb ^ 1][p][2], bf[pb ^ 1][p][3],
                                    bab0 + stb + p * 2048u + segB);
                    const uint32_t segA = ((uint32_t)((ks + 1) * 2 + ahi) ^ xkey) << 4;
                    LDMATRIX_X4(af[pa ^ 1][0], af[pa ^ 1][1], af[pa ^ 1][2], af[pa ^ 1][3],
                                aab0 + stb + segA);
                }
                #pragma unroll
                for (int p = 0; p < 4; p++) {
                    MMA16816(acc[mt][2*p],   af[pa], bf[pb][p][0], bf[pb][p][1]);
                    MMA16816(acc[mt][2*p+1], af[pa], bf[pb][p][2], bf[pb][p][3]);
                }
            }
        }
    };

    // ── prologue: 2 chunks in flight
    issue(0); issue(1);

    // ── mainloop: wait(c) → barrier → issue(c+2) → compute(c)
    //    always keep the commit-group clock ticking (empty commits at the
    //    tail) so WAIT1 provably covers chunk c's group.
    for (int c = 0; c < NCHUNK; ++c) {
        CP_WAIT1();
        __syncthreads();
        if (c + 2 < NCHUNK) issue(c + 2);
        else CP_COMMIT();
        compute(c % STAGES);
    }

    // ── epilogue: direct coalesced STG
    const int r0 = m0 + wm * 64 + (lane >> 2);
    const int c0 = n0 + wn * 64 + (lane & 3) * 2;
    float2 bb[8];
    #pragma unroll
    for (int nt = 0; nt < 8; nt++) bb[nt] = *(const float2*)(bout + c0 + nt * 8);
    #pragma unroll
    for (int mt = 0; mt < 4; mt++)
        #pragma unroll
        for (int rh = 0; rh < 2; rh++) {
            const size_t rbase = (size_t)(r0 + mt * 16 + rh * 8) * V_ + c0;
            #pragma unroll
            for (int nt = 0; nt < 8; nt++) {
                float2 v;
                v.x = (acc[mt][nt][rh * 2 + 0] + bb[nt].x) * 0.1f;
                v.y = (acc[mt][nt][rh * 2 + 1] + bb[nt].y) * 0.1f;
                *(float2*)(out + rbase + nt * 8) = v;
            }
        }
}

// ───────────── launch ─────────────
extern "C" void kernel_launch(void* const* d_in, const int* in_sizes, int n_in,
                              void* d_out, int out_size)
{
    const float* enc_in  = (const float*)d_in[0];
    const float* pred_in = (const float*)d_in[1];
    const float* W_enc   = (const float*)d_in[2];
    const float* b_enc   = (const float*)d_in[3];
    const float* W_pred  = (const float*)d_in[4];
    const float* b_pred  = (const float*)d_in[5];
    const float* W_out   = (const float*)d_in[6];
    const float* b_out   = (const float*)d_in[7];
    float* out = (float*)d_out;

    __half *genc = nullptr, *gpred = nullptr;
    cudaGetSymbolAddress((void**)&genc, g_ench);
    cudaGetSymbolAddress((void**)&gpred, g_predh);

    cudaFuncSetAttribute(joint_mma_kernel,
                         cudaFuncAttributeMaxDynamicSharedMemorySize, SMEM_DYN);

    proj_both_kernel<<<dim3(8, 25, 2), 256>>>(
        enc_in, W_enc, b_enc, pred_in, W_pred, b_pred, genc, gpred);
    joint_a_kernel<<<40256, 256>>>(W_out);
    // joint: M=160000 -> 1250 tiles of 128, N=1024 -> 8 tiles of 128
    joint_mma_kernel<<<dim3(8, 1250), 128, SMEM_DYN>>>(b_out, out);
}